// round 2
// baseline (speedup 1.0000x reference)
#include <cuda_runtime.h>
#include <cstdint>

#define EMB   1024
#define HID   2048
#define VOCAB 50257
#define NSTEP 256

// Persistent per-step state (allocations are forbidden; use __device__ globals).
__device__ float g_h[2][HID];              // double-buffered hidden state
__device__ float g_c[HID];                 // cell state (owner-only RW, single buffer)
__device__ unsigned long long g_amax[2];   // packed (ordered_float<<32)|(~row), double-buffered

// Monotone float->uint map: preserves ordering for unsigned compare.
__device__ __forceinline__ unsigned int f2ord(float f) {
    unsigned int u = __float_as_uint(f);
    return (u & 0x80000000u) ? ~u : (u | 0x80000000u);
}

__device__ __forceinline__ float sigmoidf_(float x) {
    return 1.0f / (1.0f + __expf(-x) * 0.0f + expf(-x)); // use precise expf
}

__global__ void init_kernel() {
    int i = blockIdx.x * blockDim.x + threadIdx.x;
    if (i < HID) { g_h[0][i] = 0.0f; g_c[i] = 0.0f; }
    if (i == 0) { g_amax[0] = 0ull; g_amax[1] = 0ull; }
}

// One warp per hidden unit j: computes all 4 gate dot-products (i,f,g,o rows),
// then lane 0 applies the LSTM cell update. Reads h from g_h[t&1], writes
// g_h[(t+1)&1] (double buffer -> no intra-kernel hazard).
__global__ void __launch_bounds__(256) lstm_step_kernel(
    const float* __restrict__ emb,
    const float* __restrict__ W_ih,
    const float* __restrict__ W_hh,
    const float* __restrict__ b_ih,
    const float* __restrict__ b_hh,
    int t)
{
    int warp = (blockIdx.x * blockDim.x + threadIdx.x) >> 5;
    int lane = threadIdx.x & 31;
    if (warp >= HID) return;
    int j = warp;

    // Decode previous step's greedy token (slot (t-1)&1). All threads read-only.
    int tok;
    if (t == 0) {
        tok = 0;
    } else {
        unsigned long long p = g_amax[(t + 1) & 1];
        tok = (int)(0xFFFFFFFFu - (unsigned int)(p & 0xFFFFFFFFull));
    }
    // Reset THIS step's argmax slot (t&1). Distinct from the slot read above;
    // stream ordering guarantees B(t-2) finished writing it and A(t-1) finished
    // reading it, so a single-thread reset here is race-free.
    if (blockIdx.x == 0 && threadIdx.x == 0) g_amax[t & 1] = 0ull;

    const float* __restrict__ h_in = g_h[t & 1];
    float* __restrict__ h_out = g_h[(t + 1) & 1];

    const float4* __restrict__ x4 = (const float4*)(emb + (size_t)tok * EMB);
    const float4* __restrict__ h4 = (const float4*)h_in;

    const float4* __restrict__ Wi0 = (const float4*)(W_ih + ((size_t)0 * HID + j) * EMB);
    const float4* __restrict__ Wi1 = (const float4*)(W_ih + ((size_t)1 * HID + j) * EMB);
    const float4* __restrict__ Wi2 = (const float4*)(W_ih + ((size_t)2 * HID + j) * EMB);
    const float4* __restrict__ Wi3 = (const float4*)(W_ih + ((size_t)3 * HID + j) * EMB);

    const float4* __restrict__ Wh0 = (const float4*)(W_hh + ((size_t)0 * HID + j) * HID);
    const float4* __restrict__ Wh1 = (const float4*)(W_hh + ((size_t)1 * HID + j) * HID);
    const float4* __restrict__ Wh2 = (const float4*)(W_hh + ((size_t)2 * HID + j) * HID);
    const float4* __restrict__ Wh3 = (const float4*)(W_hh + ((size_t)3 * HID + j) * HID);

    float s0 = 0.f, s1 = 0.f, s2 = 0.f, s3 = 0.f;

    #pragma unroll 4
    for (int k = lane; k < EMB / 4; k += 32) {
        float4 xv = x4[k];
        float4 a = Wi0[k]; s0 += a.x*xv.x + a.y*xv.y + a.z*xv.z + a.w*xv.w;
        float4 b = Wi1[k]; s1 += b.x*xv.x + b.y*xv.y + b.z*xv.z + b.w*xv.w;
        float4 c = Wi2[k]; s2 += c.x*xv.x + c.y*xv.y + c.z*xv.z + c.w*xv.w;
        float4 d = Wi3[k]; s3 += d.x*xv.x + d.y*xv.y + d.z*xv.z + d.w*xv.w;
    }
    #pragma unroll 4
    for (int k = lane; k < HID / 4; k += 32) {
        float4 hv = h4[k];
        float4 a = Wh0[k]; s0 += a.x*hv.x + a.y*hv.y + a.z*hv.z + a.w*hv.w;
        float4 b = Wh1[k]; s1 += b.x*hv.x + b.y*hv.y + b.z*hv.z + b.w*hv.w;
        float4 c = Wh2[k]; s2 += c.x*hv.x + c.y*hv.y + c.z*hv.z + c.w*hv.w;
        float4 d = Wh3[k]; s3 += d.x*hv.x + d.y*hv.y + d.z*hv.z + d.w*hv.w;
    }

    #pragma unroll
    for (int off = 16; off; off >>= 1) {
        s0 += __shfl_down_sync(0xffffffffu, s0, off);
        s1 += __shfl_down_sync(0xffffffffu, s1, off);
        s2 += __shfl_down_sync(0xffffffffu, s2, off);
        s3 += __shfl_down_sync(0xffffffffu, s3, off);
    }

    if (lane == 0) {
        float gi = s0 + b_ih[0 * HID + j] + b_hh[0 * HID + j];
        float gf = s1 + b_ih[1 * HID + j] + b_hh[1 * HID + j];
        float gg = s2 + b_ih[2 * HID + j] + b_hh[2 * HID + j];
        float go = s3 + b_ih[3 * HID + j] + b_hh[3 * HID + j];
        float ig = 1.0f / (1.0f + expf(-gi));
        float fg = 1.0f / (1.0f + expf(-gf));
        float gt = tanhf(gg);
        float og = 1.0f / (1.0f + expf(-go));
        float c_new = fg * g_c[j] + ig * gt;
        g_c[j] = c_new;
        h_out[j] = og * tanhf(c_new);
    }
}

// One warp per vocab row: logits = W_out @ h + b_out, write output row t,
// and fold the greedy argmax into a packed atomicMax (commutative -> deterministic).
__global__ void __launch_bounds__(256) logits_kernel(
    const float* __restrict__ W_out,
    const float* __restrict__ b_out,
    float* __restrict__ out,
    int t)
{
    int warp = (blockIdx.x * blockDim.x + threadIdx.x) >> 5;
    int lane = threadIdx.x & 31;
    if (warp >= VOCAB) return;

    const float* __restrict__ h = g_h[(t + 1) & 1];
    const float4* __restrict__ h4 = (const float4*)h;
    const float4* __restrict__ w4 = (const float4*)(W_out + (size_t)warp * HID);

    float s = 0.f;
    #pragma unroll 4
    for (int k = lane; k < HID / 4; k += 32) {
        float4 a = w4[k];
        float4 b = h4[k];
        s += a.x*b.x + a.y*b.y + a.z*b.z + a.w*b.w;
    }
    #pragma unroll
    for (int off = 16; off; off >>= 1) s += __shfl_down_sync(0xffffffffu, s, off);

    if (lane == 0) {
        s += b_out[warp];
        out[(size_t)t * VOCAB + warp] = s;
        // pack: value in high 32 (ordered), ~index in low 32 -> ties pick lowest index
        unsigned long long pk =
            ((unsigned long long)f2ord(s) << 32) |
            (unsigned long long)(0xFFFFFFFFu - (unsigned int)warp);
        atomicMax(&g_amax[t & 1], pk);
    }
}

extern "C" void kernel_launch(void* const* d_in, const int* in_sizes, int n_in,
                              void* d_out, int out_size) {
    const float* emb   = (const float*)d_in[0];
    const float* W_ih  = (const float*)d_in[1];
    const float* W_hh  = (const float*)d_in[2];
    const float* b_ih  = (const float*)d_in[3];
    const float* b_hh  = (const float*)d_in[4];
    const float* W_out = (const float*)d_in[5];
    const float* b_out = (const float*)d_in[6];
    float* out = (float*)d_out;

    init_kernel<<<(HID + 255) / 256, 256>>>();

    const int gates_blocks  = (HID * 32 + 255) / 256;     // one warp per hidden unit
    const int logits_blocks = (VOCAB * 32 + 255) / 256;   // one warp per vocab row

    for (int t = 0; t < NSTEP; t++) {
        lstm_step_kernel<<<gates_blocks, 256>>>(emb, W_ih, W_hh, b_ih, b_hh, t);
        logits_kernel<<<logits_blocks, 256>>>(W_out, b_out, out, t);
    }
}

// round 5
// speedup vs baseline: 1.0507x; 1.0507x over previous
#include <cuda_runtime.h>
#include <cstdint>

#define EMB   1024
#define HID   2048
#define VOCAB 50257
#define NSTEP 256
#define NGATE (4 * HID)

// Persistent per-step state (allocations forbidden -> __device__ globals).
__device__ float g_h[2][HID];              // double-buffered hidden state
__device__ float g_c[HID];                 // cell state
__device__ float g_gates[NGATE];           // gate pre-activations for current step
__device__ unsigned int g_ticket;          // last-block-done ticket
__device__ unsigned long long g_amax[2];   // packed (ordered_float<<32)|(~row)

// Monotone float->uint map: preserves ordering under unsigned compare.
__device__ __forceinline__ unsigned int f2ord(float f) {
    unsigned int u = __float_as_uint(f);
    return (u & 0x80000000u) ? ~u : (u | 0x80000000u);
}

__global__ void init_kernel() {
    int i = blockIdx.x * blockDim.x + threadIdx.x;
    if (i < HID) { g_h[0][i] = 0.0f; g_c[i] = 0.0f; }
    if (i == 0) { g_amax[0] = 0ull; g_amax[1] = 0ull; g_ticket = 0u; }
}

// One warp per gate row r in [0, 8192): s = W_ih[r,:]@x + W_hh[r,:]@h.
// Last block to finish applies the LSTM cell update for all 2048 units.
__global__ void __launch_bounds__(256) gates_kernel(
    const float* __restrict__ emb,
    const float* __restrict__ W_ih,
    const float* __restrict__ W_hh,
    const float* __restrict__ b_ih,
    const float* __restrict__ b_hh,
    int t)
{
    const int warp = (blockIdx.x * blockDim.x + threadIdx.x) >> 5;
    const int lane = threadIdx.x & 31;
    const int r = warp;   // gate row 0..8191

    // Decode previous step's greedy token.
    int tok;
    if (t == 0) {
        tok = 0;
    } else {
        unsigned long long p = g_amax[(t + 1) & 1];
        tok = (int)(0xFFFFFFFFu - (unsigned int)(p & 0xFFFFFFFFull));
    }
    // Reset THIS step's argmax slot (only read/written later by logits kernel,
    // which is stream-ordered after us).
    if (blockIdx.x == 0 && threadIdx.x == 0) g_amax[t & 1] = 0ull;

    const float* __restrict__ h_in = g_h[t & 1];
    const float4* __restrict__ x4 = (const float4*)(emb + (size_t)tok * EMB);
    const float4* __restrict__ h4 = (const float4*)h_in;
    const float4* __restrict__ wi = (const float4*)(W_ih + (size_t)r * EMB);
    const float4* __restrict__ wh = (const float4*)(W_hh + (size_t)r * HID);

    float s = 0.f;
    #pragma unroll
    for (int k = 0; k < EMB / 4 / 32; k++) {       // 8 iters
        int idx = lane + 32 * k;
        float4 w = __ldcs(&wi[idx]);               // streamed, evict-first
        float4 v = x4[idx];
        s += w.x * v.x + w.y * v.y + w.z * v.z + w.w * v.w;
    }
    #pragma unroll
    for (int k = 0; k < HID / 4 / 32; k++) {       // 16 iters
        int idx = lane + 32 * k;
        float4 w = __ldcs(&wh[idx]);
        float4 v = h4[idx];
        s += w.x * v.x + w.y * v.y + w.z * v.z + w.w * v.w;
    }

    #pragma unroll
    for (int off = 16; off; off >>= 1) s += __shfl_down_sync(0xffffffffu, s, off);
    if (lane == 0) g_gates[r] = s;

    // Last-block-done: the final block applies the cell update (no extra launch).
    __threadfence();
    __syncthreads();
    __shared__ bool s_last;
    if (threadIdx.x == 0) {
        unsigned int old = atomicAdd(&g_ticket, 1u);
        s_last = (old == gridDim.x - 1);
    }
    __syncthreads();
    if (s_last) {
        float* __restrict__ h_out = g_h[(t + 1) & 1];
        for (int j = threadIdx.x; j < HID; j += blockDim.x) {
            float gi = g_gates[0 * HID + j] + b_ih[0 * HID + j] + b_hh[0 * HID + j];
            float gf = g_gates[1 * HID + j] + b_ih[1 * HID + j] + b_hh[1 * HID + j];
            float gg = g_gates[2 * HID + j] + b_ih[2 * HID + j] + b_hh[2 * HID + j];
            float go = g_gates[3 * HID + j] + b_ih[3 * HID + j] + b_hh[3 * HID + j];
            float ig = 1.0f / (1.0f + expf(-gi));
            float fg = 1.0f / (1.0f + expf(-gf));
            float gt = tanhf(gg);
            float og = 1.0f / (1.0f + expf(-go));
            float c_new = fg * g_c[j] + ig * gt;
            g_c[j] = c_new;
            h_out[j] = og * tanhf(c_new);
        }
        if (threadIdx.x == 0) g_ticket = 0u;   // reset for next step
    }
}

// One warp per vocab row; per-block smem argmax reduction -> one atomic/block.
__global__ void __launch_bounds__(256) logits_kernel(
    const float* __restrict__ W_out,
    const float* __restrict__ b_out,
    float* __restrict__ out,
    int t)
{
    const int warp_in_blk = threadIdx.x >> 5;
    const int lane = threadIdx.x & 31;
    const int row = blockIdx.x * 8 + warp_in_blk;

    __shared__ unsigned long long s_key[8];

    const float* __restrict__ h = g_h[(t + 1) & 1];
    const float4* __restrict__ h4 = (const float4*)h;

    unsigned long long key = 0ull;
    if (row < VOCAB) {
        const float4* __restrict__ w4 = (const float4*)(W_out + (size_t)row * HID);
        float s = 0.f;
        #pragma unroll 8
        for (int k = lane; k < HID / 4; k += 32) {
            float4 a = __ldcs(&w4[k]);             // streamed, evict-first
            float4 b = h4[k];
            s += a.x * b.x + a.y * b.y + a.z * b.z + a.w * b.w;
        }
        #pragma unroll
        for (int off = 16; off; off >>= 1) s += __shfl_down_sync(0xffffffffu, s, off);
        if (lane == 0) {
            s += b_out[row];
            out[(size_t)t * VOCAB + row] = s;
            key = ((unsigned long long)f2ord(s) << 32) |
                  (unsigned long long)(0xFFFFFFFFu - (unsigned int)row);
        }
    }
    if (lane == 0) s_key[warp_in_blk] = key;
    __syncthreads();
    if (threadIdx.x == 0) {
        unsigned long long best = s_key[0];
        #pragma unroll
        for (int i = 1; i < 8; i++) if (s_key[i] > best) best = s_key[i];
        atomicMax(&g_amax[t & 1], best);
    }
}

extern "C" void kernel_launch(void* const* d_in, const int* in_sizes, int n_in,
                              void* d_out, int out_size) {
    const float* emb   = (const float*)d_in[0];
    const float* W_ih  = (const float*)d_in[1];
    const float* W_hh  = (const float*)d_in[2];
    const float* b_ih  = (const float*)d_in[3];
    const float* b_hh  = (const float*)d_in[4];
    const float* W_out = (const float*)d_in[5];
    const float* b_out = (const float*)d_in[6];
    float* out = (float*)d_out;

    init_kernel<<<(HID + 255) / 256, 256>>>();

    const int gates_blocks  = NGATE / 8;                 // 8 warps/block, 1024 blocks
    const int logits_blocks = (VOCAB + 7) / 8;           // 8 rows/block

    for (int t = 0; t < NSTEP; t++) {
        gates_kernel<<<gates_blocks, 256>>>(emb, W_ih, W_hh, b_ih, b_hh, t);
        logits_kernel<<<logits_blocks, 256>>>(W_out, b_out, out, t);
    }
}

// round 6
// speedup vs baseline: 1.1542x; 1.0985x over previous
#include <cuda_runtime.h>
#include <cstdint>

#define EMB   1024
#define HID   2048
#define VOCAB 50257
#define NSTEP 256
#define QK    4            // K-dimension split for gates kernel

// Persistent per-step state (allocations forbidden -> __device__ globals).
__device__ float g_h[2][HID];              // double-buffered hidden state
__device__ float g_c[HID];                 // cell state
__device__ float g_part[QK][4][HID];       // partial gate dots [quarter][gate][unit]
__device__ unsigned long long g_amax[2];   // packed (ordered_float<<32)|(~row)

// Monotone float->uint map: preserves ordering under unsigned compare.
__device__ __forceinline__ unsigned int f2ord(float f) {
    unsigned int u = __float_as_uint(f);
    return (u & 0x80000000u) ? ~u : (u | 0x80000000u);
}

__global__ void init_kernel() {
    int i = blockIdx.x * blockDim.x + threadIdx.x;
    if (i < HID) { g_h[0][i] = 0.0f; g_c[i] = 0.0f; }
    if (i == 0) { g_amax[0] = 0ull; g_amax[1] = 0ull; }
}

// Warp w -> (unit j = w>>2, quarter q = w&3). Computes the 4 gate-row partial
// dots of unit j over K-quarter q (EMB quarter: 256 floats, HID quarter: 512).
// 4 interleaved weight streams per warp -> high per-warp MLP; no tail work.
__global__ void __launch_bounds__(256) gates_kernel(
    const float* __restrict__ emb,
    const float* __restrict__ W_ih,
    const float* __restrict__ W_hh,
    int t)
{
    const int warp = blockIdx.x * 8 + (threadIdx.x >> 5);
    const int lane = threadIdx.x & 31;
    const int j = warp >> 2;     // hidden unit 0..2047
    const int q = warp & 3;      // K quarter 0..3

    // Decode previous step's greedy token.
    int tok;
    if (t == 0) {
        tok = 0;
    } else {
        unsigned long long p = g_amax[(t + 1) & 1];
        tok = (int)(0xFFFFFFFFu - (unsigned int)(p & 0xFFFFFFFFull));
    }
    // Reset THIS step's argmax slot (written later by stream-ordered logits kernel).
    if (blockIdx.x == 0 && threadIdx.x == 0) g_amax[t & 1] = 0ull;

    const float4* __restrict__ x4 = (const float4*)(emb + (size_t)tok * EMB) + q * (EMB / 4 / QK);
    const float4* __restrict__ h4 = (const float4*)g_h[t & 1] + q * (HID / 4 / QK);

    const float4* __restrict__ wi0 = (const float4*)(W_ih + ((size_t)0 * HID + j) * EMB) + q * (EMB / 4 / QK);
    const float4* __restrict__ wi1 = (const float4*)(W_ih + ((size_t)1 * HID + j) * EMB) + q * (EMB / 4 / QK);
    const float4* __restrict__ wi2 = (const float4*)(W_ih + ((size_t)2 * HID + j) * EMB) + q * (EMB / 4 / QK);
    const float4* __restrict__ wi3 = (const float4*)(W_ih + ((size_t)3 * HID + j) * EMB) + q * (EMB / 4 / QK);

    const float4* __restrict__ wh0 = (const float4*)(W_hh + ((size_t)0 * HID + j) * HID) + q * (HID / 4 / QK);
    const float4* __restrict__ wh1 = (const float4*)(W_hh + ((size_t)1 * HID + j) * HID) + q * (HID / 4 / QK);
    const float4* __restrict__ wh2 = (const float4*)(W_hh + ((size_t)2 * HID + j) * HID) + q * (HID / 4 / QK);
    const float4* __restrict__ wh3 = (const float4*)(W_hh + ((size_t)3 * HID + j) * HID) + q * (HID / 4 / QK);

    float s0 = 0.f, s1 = 0.f, s2 = 0.f, s3 = 0.f;

    #pragma unroll
    for (int m = 0; m < EMB / 4 / QK / 32; m++) {        // 2 iters
        int idx = lane + 32 * m;
        float4 v = x4[idx];
        float4 a = __ldcs(&wi0[idx]); s0 += a.x*v.x + a.y*v.y + a.z*v.z + a.w*v.w;
        float4 b = __ldcs(&wi1[idx]); s1 += b.x*v.x + b.y*v.y + b.z*v.z + b.w*v.w;
        float4 c = __ldcs(&wi2[idx]); s2 += c.x*v.x + c.y*v.y + c.z*v.z + c.w*v.w;
        float4 d = __ldcs(&wi3[idx]); s3 += d.x*v.x + d.y*v.y + d.z*v.z + d.w*v.w;
    }
    #pragma unroll
    for (int m = 0; m < HID / 4 / QK / 32; m++) {        // 4 iters
        int idx = lane + 32 * m;
        float4 v = h4[idx];
        float4 a = __ldcs(&wh0[idx]); s0 += a.x*v.x + a.y*v.y + a.z*v.z + a.w*v.w;
        float4 b = __ldcs(&wh1[idx]); s1 += b.x*v.x + b.y*v.y + b.z*v.z + b.w*v.w;
        float4 c = __ldcs(&wh2[idx]); s2 += c.x*v.x + c.y*v.y + c.z*v.z + c.w*v.w;
        float4 d = __ldcs(&wh3[idx]); s3 += d.x*v.x + d.y*v.y + d.z*v.z + d.w*v.w;
    }

    #pragma unroll
    for (int off = 16; off; off >>= 1) {
        s0 += __shfl_down_sync(0xffffffffu, s0, off);
        s1 += __shfl_down_sync(0xffffffffu, s1, off);
        s2 += __shfl_down_sync(0xffffffffu, s2, off);
        s3 += __shfl_down_sync(0xffffffffu, s3, off);
    }
    if (lane == 0) {
        g_part[q][0][j] = s0;
        g_part[q][1][j] = s1;
        g_part[q][2][j] = s2;
        g_part[q][3][j] = s3;
    }
}

// One thread per hidden unit: sum partials + biases, apply LSTM cell (precise math).
__global__ void __launch_bounds__(256) cell_kernel(
    const float* __restrict__ b_ih,
    const float* __restrict__ b_hh,
    int t)
{
    int j = blockIdx.x * blockDim.x + threadIdx.x;
    if (j >= HID) return;

    float gs[4];
    #pragma unroll
    for (int g = 0; g < 4; g++) {
        gs[g] = ((g_part[0][g][j] + g_part[1][g][j]) +
                 (g_part[2][g][j] + g_part[3][g][j])) +
                b_ih[g * HID + j] + b_hh[g * HID + j];
    }
    float ig = 1.0f / (1.0f + expf(-gs[0]));
    float fg = 1.0f / (1.0f + expf(-gs[1]));
    float gt = tanhf(gs[2]);
    float og = 1.0f / (1.0f + expf(-gs[3]));
    float c_new = fg * g_c[j] + ig * gt;
    g_c[j] = c_new;
    g_h[(t + 1) & 1][j] = og * tanhf(c_new);
}

// One warp per vocab row; per-block smem argmax reduction -> one atomic/block.
__global__ void __launch_bounds__(256) logits_kernel(
    const float* __restrict__ W_out,
    const float* __restrict__ b_out,
    float* __restrict__ out,
    int t)
{
    const int warp_in_blk = threadIdx.x >> 5;
    const int lane = threadIdx.x & 31;
    const int row = blockIdx.x * 8 + warp_in_blk;

    __shared__ unsigned long long s_key[8];

    const float* __restrict__ h = g_h[(t + 1) & 1];
    const float4* __restrict__ h4 = (const float4*)h;

    unsigned long long key = 0ull;
    if (row < VOCAB) {
        const float4* __restrict__ w4 = (const float4*)(W_out + (size_t)row * HID);
        float s = 0.f;
        #pragma unroll 8
        for (int k = lane; k < HID / 4; k += 32) {
            float4 a = __ldcs(&w4[k]);             // streamed, evict-first
            float4 b = h4[k];
            s += a.x * b.x + a.y * b.y + a.z * b.z + a.w * b.w;
        }
        #pragma unroll
        for (int off = 16; off; off >>= 1) s += __shfl_down_sync(0xffffffffu, s, off);
        if (lane == 0) {
            s += b_out[row];
            out[(size_t)t * VOCAB + row] = s;
            key = ((unsigned long long)f2ord(s) << 32) |
                  (unsigned long long)(0xFFFFFFFFu - (unsigned int)row);
        }
    }
    if (lane == 0) s_key[warp_in_blk] = key;
    __syncthreads();
    if (threadIdx.x == 0) {
        unsigned long long best = s_key[0];
        #pragma unroll
        for (int i = 1; i < 8; i++) if (s_key[i] > best) best = s_key[i];
        atomicMax(&g_amax[t & 1], best);
    }
}

extern "C" void kernel_launch(void* const* d_in, const int* in_sizes, int n_in,
                              void* d_out, int out_size) {
    const float* emb   = (const float*)d_in[0];
    const float* W_ih  = (const float*)d_in[1];
    const float* W_hh  = (const float*)d_in[2];
    const float* b_ih  = (const float*)d_in[3];
    const float* b_hh  = (const float*)d_in[4];
    const float* W_out = (const float*)d_in[5];
    const float* b_out = (const float*)d_in[6];
    float* out = (float*)d_out;

    init_kernel<<<(HID + 255) / 256, 256>>>();

    const int gates_blocks  = (HID * QK * 32) / 256;     // 1024 blocks, 8192 warps
    const int cell_blocks   = (HID + 255) / 256;         // 8 blocks
    const int logits_blocks = (VOCAB + 7) / 8;           // 8 rows/block

    for (int t = 0; t < NSTEP; t++) {
        gates_kernel<<<gates_blocks, 256>>>(emb, W_ih, W_hh, t);
        cell_kernel<<<cell_blocks, 256>>>(b_ih, b_hh, t);
        logits_kernel<<<logits_blocks, 256>>>(W_out, b_out, out, t);
    }
}